// round 2
// baseline (speedup 1.0000x reference)
#include <cuda_runtime.h>
#include <cuda_bf16.h>
#include <cstdint>

#define Bc   16
#define Nc   10000
#define Dc   128
#define TOKc (Bc * Nc)          // 160000
#define EPSc 1e-5f

// ---------------- scratch (no allocations allowed) ----------------
__device__ float g_hpos[(size_t)TOKc * Dc];
__device__ float g_A   [(size_t)TOKc * Dc];   // reused as msg
__device__ float g_C   [(size_t)TOKc * Dc];   // reused as t
__device__ float g_P   [(size_t)TOKc * Dc];
__device__ float g_ys  [(size_t)TOKc * Dc];
__device__ int   g_tour[TOKc];
__device__ int   g_is64;

__device__ __forceinline__ float silu_f(float x) { return x / (1.f + __expf(-x)); }

// ---- tour dtype detection: int64 values < 2^31 have zero odd 32-bit words ----
__global__ void k_detect(const int* __restrict__ tour_raw) {
    // values are permutation entries < 10000; if int64, words 1,3,5,... are 0.
    // if int32, odd words are distinct permutation entries (cannot all be 0).
    int allzero = 1;
    for (int i = 1; i < 129; i += 2) allzero &= (tour_raw[i] == 0);
    g_is64 = allzero;
}

__global__ void k_convert(const int* __restrict__ tour_raw, int* __restrict__ tour) {
    int t = blockIdx.x * blockDim.x + threadIdx.x;
    if (t >= TOKc) return;
    tour[t] = g_is64 ? tour_raw[2 * t] : tour_raw[t];
}

// ---------------- gather: hpos[b,i,:] = h[b, tour[b,i], :] ----------------
__global__ void k_gather(const float* __restrict__ h,
                         const int* __restrict__ tour,
                         float* __restrict__ hpos) {
    int tid = blockIdx.x * blockDim.x + threadIdx.x;
    if (tid >= TOKc * 32) return;                 // float4 lanes
    int token = tid >> 5, c = tid & 31;
    int b = token / Nc;
    int node = tour[token];
    const float4* h4 = (const float4*)h;
    float4* o4 = (float4*)hpos;
    o4[(size_t)token * 32 + c] = h4[((size_t)b * Nc + node) * 32 + c];
}

// ------- ys = silu(A + C[i-1] + b1m) + silu(A + C[i+1] + b1m) (roll per batch) -------
__global__ void k_roll(const float* __restrict__ A, const float* __restrict__ C,
                       const float* __restrict__ b1m, float* __restrict__ ys) {
    int tid = blockIdx.x * blockDim.x + threadIdx.x;
    if (tid >= TOKc * 32) return;
    int token = tid >> 5, c = tid & 31;
    int b = token / Nc, i = token - b * Nc;
    int ip = b * Nc + (i == 0 ? Nc - 1 : i - 1);
    int in_ = b * Nc + (i == Nc - 1 ? 0 : i + 1);
    const float4* A4 = (const float4*)A;
    const float4* C4 = (const float4*)C;
    float4 a  = A4[(size_t)token * 32 + c];
    float4 cp = C4[(size_t)ip * 32 + c];
    float4 cn = C4[(size_t)in_ * 32 + c];
    float4 bb = ((const float4*)b1m)[c];
    float4 r;
    r.x = silu_f(a.x + cp.x + bb.x) + silu_f(a.x + cn.x + bb.x);
    r.y = silu_f(a.y + cp.y + bb.y) + silu_f(a.y + cn.y + bb.y);
    r.z = silu_f(a.z + cp.z + bb.z) + silu_f(a.z + cn.z + bb.z);
    r.w = silu_f(a.w + cp.w + bb.w) + silu_f(a.w + cn.w + bb.w);
    ((float4*)ys)[(size_t)token * 32 + c] = r;
}

// ---------------- GEMM: out[row, 0:128] = X[row, 0:128] @ W[128,128] + epilogue ----------------
// MODE 0: out = acc
// MODE 1: out = acc + biasScale * bias
// MODE 2: out = silu(acc + add + bias)
// MODE 3: r = acc + add + bias; LayerNorm over D; scatter out[b, tour[row], :] = r*gamma+beta
template <int MODE>
__global__ void __launch_bounds__(256)
k_gemm(const float* __restrict__ X, const float* __restrict__ W,
       const float* __restrict__ bias, float biasScale,
       const float* __restrict__ add, float* __restrict__ out,
       const int* __restrict__ tour,
       const float* __restrict__ gamma, const float* __restrict__ beta) {
    __shared__ float Xs[64][33];
    __shared__ float Ws[32][128];
    __shared__ float red1[64][4];
    __shared__ float red2[64][4];

    const int tid = threadIdx.x;
    const int m = tid >> 2;          // 0..63 token within tile
    const int q = tid & 3;           // quarter of output row
    const int n0 = q * 32;
    const int m0 = blockIdx.x * 64;

    float acc[32];
#pragma unroll
    for (int j = 0; j < 32; j++) acc[j] = 0.f;

    for (int k0 = 0; k0 < 128; k0 += 32) {
        // X tile: 64 rows x 32 cols = 512 float4 loads
        for (int f = tid; f < 512; f += 256) {
            int r = f >> 3, c4 = f & 7;
            float4 v = *(const float4*)&X[(size_t)(m0 + r) * 128 + k0 + c4 * 4];
            Xs[r][c4 * 4 + 0] = v.x; Xs[r][c4 * 4 + 1] = v.y;
            Xs[r][c4 * 4 + 2] = v.z; Xs[r][c4 * 4 + 3] = v.w;
        }
        // W tile: 32 rows x 128 cols = 1024 float4 loads
        for (int f = tid; f < 1024; f += 256) {
            int r = f >> 5, c4 = f & 31;
            *(float4*)&Ws[r][c4 * 4] = *(const float4*)&W[(size_t)(k0 + r) * 128 + c4 * 4];
        }
        __syncthreads();
#pragma unroll
        for (int kk = 0; kk < 32; kk++) {
            float xv = Xs[m][kk];
#pragma unroll
            for (int j = 0; j < 32; j++) acc[j] += xv * Ws[kk][n0 + j];
        }
        __syncthreads();
    }

    const int row = m0 + m;          // global token index (TOKc % 64 == 0)

    if (MODE == 0) {
        float* o = &out[(size_t)row * 128 + n0];
#pragma unroll
        for (int j = 0; j < 32; j += 4) {
            float4 v = make_float4(acc[j], acc[j+1], acc[j+2], acc[j+3]);
            *(float4*)&o[j] = v;
        }
    } else if (MODE == 1) {
        float* o = &out[(size_t)row * 128 + n0];
#pragma unroll
        for (int j = 0; j < 32; j += 4) {
            float4 bb = *(const float4*)&bias[n0 + j];
            float4 v = make_float4(acc[j] + biasScale * bb.x, acc[j+1] + biasScale * bb.y,
                                   acc[j+2] + biasScale * bb.z, acc[j+3] + biasScale * bb.w);
            *(float4*)&o[j] = v;
        }
    } else if (MODE == 2) {
        float* o = &out[(size_t)row * 128 + n0];
        const float* a = &add[(size_t)row * 128 + n0];
#pragma unroll
        for (int j = 0; j < 32; j += 4) {
            float4 bb = *(const float4*)&bias[n0 + j];
            float4 av = *(const float4*)&a[j];
            float4 v;
            v.x = silu_f(acc[j]   + av.x + bb.x);
            v.y = silu_f(acc[j+1] + av.y + bb.y);
            v.z = silu_f(acc[j+2] + av.z + bb.z);
            v.w = silu_f(acc[j+3] + av.w + bb.w);
            *(float4*)&o[j] = v;
        }
    } else { // MODE 3: residual + LayerNorm + scatter
        const float* a = &add[(size_t)row * 128 + n0];
        float s = 0.f, ss = 0.f;
#pragma unroll
        for (int j = 0; j < 32; j++) {
            float r = acc[j] + bias[n0 + j] + a[j];
            acc[j] = r;
            s += r; ss += r * r;
        }
        red1[m][q] = s; red2[m][q] = ss;
        __syncthreads();
        float sum = red1[m][0] + red1[m][1] + red1[m][2] + red1[m][3];
        float sqs = red2[m][0] + red2[m][1] + red2[m][2] + red2[m][3];
        float mu = sum * (1.f / 128.f);
        float var = sqs * (1.f / 128.f) - mu * mu;
        float inv = rsqrtf(var + EPSc);
        int b = row / Nc;
        int node = tour[row];
        float* o = &out[((size_t)b * Nc + node) * 128 + n0];
#pragma unroll
        for (int j = 0; j < 32; j += 4) {
            float4 gv = *(const float4*)&gamma[n0 + j];
            float4 bv = *(const float4*)&beta[n0 + j];
            float4 v;
            v.x = (acc[j]   - mu) * inv * gv.x + bv.x;
            v.y = (acc[j+1] - mu) * inv * gv.y + bv.y;
            v.z = (acc[j+2] - mu) * inv * gv.z + bv.z;
            v.w = (acc[j+3] - mu) * inv * gv.w + bv.w;
            *(float4*)&o[j] = v;
        }
    }
}

extern "C" void kernel_launch(void* const* d_in, const int* in_sizes, int n_in,
                              void* d_out, int out_size) {
    const float* h        = (const float*)d_in[0];
    const int*   tour_raw = (const int*)d_in[1];
    const float* W1m      = (const float*)d_in[2];
    const float* b1m      = (const float*)d_in[3];
    const float* W2m      = (const float*)d_in[4];
    const float* b2m      = (const float*)d_in[5];
    const float* W1u      = (const float*)d_in[6];
    const float* b1u      = (const float*)d_in[7];
    const float* W2u      = (const float*)d_in[8];
    const float* b2u      = (const float*)d_in[9];
    const float* gamma    = (const float*)d_in[10];
    const float* beta     = (const float*)d_in[11];
    float* out            = (float*)d_out;

    float *hpos, *A, *C, *P, *ys;
    int* tour;
    cudaGetSymbolAddress((void**)&hpos, g_hpos);
    cudaGetSymbolAddress((void**)&A,    g_A);
    cudaGetSymbolAddress((void**)&C,    g_C);
    cudaGetSymbolAddress((void**)&P,    g_P);
    cudaGetSymbolAddress((void**)&ys,   g_ys);
    cudaGetSymbolAddress((void**)&tour, g_tour);
    float* msg = A;   // A dead after k_roll
    float* t   = C;   // C dead after k_roll

    const int EW_BLOCKS = (TOKc * 32 + 255) / 256;   // 20000
    const int GEMM_BLOCKS = TOKc / 64;               // 2500

    // 0. normalize tour dtype (int32 or int64) into g_tour
    k_detect<<<1, 1>>>(tour_raw);
    k_convert<<<(TOKc + 255) / 256, 256>>>(tour_raw, tour);
    // 1. gather
    k_gather<<<EW_BLOCKS, 256>>>(h, tour, hpos);
    // 2. A = hpos@W1m[0:128], C = hpos@W1m[128:256], P = hpos@W1u[0:128]
    k_gemm<0><<<GEMM_BLOCKS, 256>>>(hpos, W1m,             nullptr, 0.f, nullptr, A, nullptr, nullptr, nullptr);
    k_gemm<0><<<GEMM_BLOCKS, 256>>>(hpos, W1m + 128 * 128, nullptr, 0.f, nullptr, C, nullptr, nullptr, nullptr);
    k_gemm<0><<<GEMM_BLOCKS, 256>>>(hpos, W1u,             nullptr, 0.f, nullptr, P, nullptr, nullptr, nullptr);
    // 3. ys = silu(A + C[i-1] + b1m) + silu(A + C[i+1] + b1m)
    k_roll<<<EW_BLOCKS, 256>>>(A, C, b1m, ys);
    // 4. msg = ys@W2m + 2*b2m
    k_gemm<1><<<GEMM_BLOCKS, 256>>>(ys, W2m, b2m, 2.f, nullptr, msg, nullptr, nullptr, nullptr);
    // 5. t = silu(P + msg@W1u[128:256] + b1u)
    k_gemm<2><<<GEMM_BLOCKS, 256>>>(msg, W1u + 128 * 128, b1u, 1.f, P, t, nullptr, nullptr, nullptr);
    // 6. out[tour] = LN(hpos + t@W2u + b2u) * gamma + beta
    k_gemm<3><<<GEMM_BLOCKS, 256>>>(t, W2u, b2u, 1.f, hpos, out, tour, gamma, beta);
}

// round 3
// speedup vs baseline: 7.5490x; 7.5490x over previous
#include <cuda_runtime.h>
#include <cuda_bf16.h>
#include <cstdint>

#define Bc   16
#define Nc   10000
#define Dc   128
#define TOKc (Bc * Nc)          // 160000
#define EPSc 1e-5f
#define KC   32

// ---------------- scratch (no allocations allowed) ----------------
__device__ float g_hpos[(size_t)TOKc * Dc];
__device__ float g_A   [(size_t)TOKc * Dc];   // A, later t
__device__ float g_C   [(size_t)TOKc * Dc];   // C
__device__ float g_P   [(size_t)TOKc * Dc];   // P
__device__ float g_ys  [(size_t)TOKc * Dc];   // msg
__device__ int   g_tour[TOKc];
__device__ int   g_is64;

__device__ __forceinline__ float silu_f(float x) { return x / (1.f + __expf(-x)); }

// ---- tour dtype detection: int64 values < 2^31 have zero odd 32-bit words ----
__global__ void k_detect(const int* __restrict__ tour_raw) {
    int allzero = 1;
    for (int i = 1; i < 129; i += 2) allzero &= (tour_raw[i] == 0);
    g_is64 = allzero;
}
__global__ void k_convert(const int* __restrict__ tour_raw, int* __restrict__ tour) {
    int t = blockIdx.x * blockDim.x + threadIdx.x;
    if (t >= TOKc) return;
    tour[t] = g_is64 ? tour_raw[2 * t] : tour_raw[t];
}

// ================= fused GEMM =================
// Tile: 64 tokens x 128 outputs. 256 threads: tn = tid&15 (col groups), tm = tid>>4 (token groups).
// Thread computes 4 tokens x 8 cols (cols tn*4..+3 and 64+tn*4..+3) per weight set.
// PRO: 0 = direct X rows, 1 = gather via tour (+ write hpos), 2 = roll (ys from A,C,b1m)
// EPI: 0 = plain store (NSETS outputs), 1 = acc + biasScale*bias,
//      2 = silu(acc + bias + add), 3 = LayerNorm(acc + bias + add) * gamma + beta, scatter via tour
template<int NSETS, int PRO, int EPI>
__global__ void __launch_bounds__(256, 2)
k_fused(const float* __restrict__ X, const float* __restrict__ X2,
        const float* __restrict__ W0p, const float* __restrict__ W1p,
        const float* __restrict__ bias, const float* __restrict__ rbias, float biasScale,
        const float* __restrict__ add,
        float* __restrict__ out0, float* __restrict__ out1,
        float* __restrict__ hpos,
        const int* __restrict__ tour,
        const float* __restrict__ gamma, const float* __restrict__ beta) {
    __shared__ float Xs[KC][72];               // transposed X tile, padded
    __shared__ float Ws[NSETS][KC][128];

    const int tid = threadIdx.x;
    const int tn = tid & 15;
    const int tm = tid >> 4;
    const int m0 = blockIdx.x * 64;

    float acc[NSETS][4][8];
#pragma unroll
    for (int s = 0; s < NSETS; s++)
#pragma unroll
        for (int tt = 0; tt < 4; tt++)
#pragma unroll
            for (int e = 0; e < 8; e++) acc[s][tt][e] = 0.f;

    for (int k0 = 0; k0 < 128; k0 += KC) {
        // ---- load X tile (64 rows x KC cols), store transposed ----
#pragma unroll
        for (int ff = 0; ff < 2; ff++) {
            int f = tid + ff * 256;            // 0..511
            int r = f >> 3, c4 = f & 7;
            int t = m0 + r;
            int col = k0 + c4 * 4;
            float4 v;
            if (PRO == 0) {
                v = *(const float4*)&X[(size_t)t * 128 + col];
            } else if (PRO == 1) {
                int b = t / Nc;
                int node = tour[t];
                v = *(const float4*)&X[((size_t)b * Nc + node) * 128 + col];
                *(float4*)&hpos[(size_t)t * 128 + col] = v;
            } else {
                int b = t / Nc, i = t - b * Nc;
                int tp = (i == 0)      ? t + Nc - 1 : t - 1;
                int tx = (i == Nc - 1) ? t - Nc + 1 : t + 1;
                float4 a  = *(const float4*)&X [(size_t)t  * 128 + col];
                float4 cp = *(const float4*)&X2[(size_t)tp * 128 + col];
                float4 cn = *(const float4*)&X2[(size_t)tx * 128 + col];
                float4 bb = *(const float4*)&rbias[col];
                v.x = silu_f(a.x + cp.x + bb.x) + silu_f(a.x + cn.x + bb.x);
                v.y = silu_f(a.y + cp.y + bb.y) + silu_f(a.y + cn.y + bb.y);
                v.z = silu_f(a.z + cp.z + bb.z) + silu_f(a.z + cn.z + bb.z);
                v.w = silu_f(a.w + cp.w + bb.w) + silu_f(a.w + cn.w + bb.w);
            }
            Xs[c4 * 4 + 0][r] = v.x;
            Xs[c4 * 4 + 1][r] = v.y;
            Xs[c4 * 4 + 2][r] = v.z;
            Xs[c4 * 4 + 3][r] = v.w;
        }
        // ---- load W tiles ----
#pragma unroll
        for (int ff = 0; ff < NSETS * 4; ff++) {
            int f = tid + ff * 256;            // < NSETS*1024
            int s = f >> 10;
            int r = (f >> 5) & 31;
            int c4 = f & 31;
            const float* Wp = (s == 0) ? W0p : W1p;
            *(float4*)&Ws[s][r][c4 * 4] = *(const float4*)&Wp[(size_t)(k0 + r) * 128 + c4 * 4];
        }
        __syncthreads();
        // ---- register-blocked outer product ----
#pragma unroll
        for (int kk = 0; kk < KC; kk++) {
            float4 xm4 = *(const float4*)&Xs[kk][tm * 4];
            float xv[4] = {xm4.x, xm4.y, xm4.z, xm4.w};
#pragma unroll
            for (int s = 0; s < NSETS; s++) {
                float4 wa = *(const float4*)&Ws[s][kk][tn * 4];
                float4 wb = *(const float4*)&Ws[s][kk][64 + tn * 4];
#pragma unroll
                for (int tt = 0; tt < 4; tt++) {
                    acc[s][tt][0] += xv[tt] * wa.x;
                    acc[s][tt][1] += xv[tt] * wa.y;
                    acc[s][tt][2] += xv[tt] * wa.z;
                    acc[s][tt][3] += xv[tt] * wa.w;
                    acc[s][tt][4] += xv[tt] * wb.x;
                    acc[s][tt][5] += xv[tt] * wb.y;
                    acc[s][tt][6] += xv[tt] * wb.z;
                    acc[s][tt][7] += xv[tt] * wb.w;
                }
            }
        }
        __syncthreads();
    }

    const int cl = tn * 4, ch = 64 + tn * 4;

    if constexpr (EPI == 0) {
#pragma unroll
        for (int s = 0; s < NSETS; s++) {
            float* o = (s == 0) ? out0 : out1;
#pragma unroll
            for (int tt = 0; tt < 4; tt++) {
                size_t t = m0 + tm * 4 + tt;
                *(float4*)&o[t * 128 + cl] = make_float4(acc[s][tt][0], acc[s][tt][1], acc[s][tt][2], acc[s][tt][3]);
                *(float4*)&o[t * 128 + ch] = make_float4(acc[s][tt][4], acc[s][tt][5], acc[s][tt][6], acc[s][tt][7]);
            }
        }
    } else if constexpr (EPI == 1) {
        float4 blo = *(const float4*)&bias[cl];
        float4 bhi = *(const float4*)&bias[ch];
#pragma unroll
        for (int tt = 0; tt < 4; tt++) {
            size_t t = m0 + tm * 4 + tt;
            *(float4*)&out0[t * 128 + cl] = make_float4(
                acc[0][tt][0] + biasScale * blo.x, acc[0][tt][1] + biasScale * blo.y,
                acc[0][tt][2] + biasScale * blo.z, acc[0][tt][3] + biasScale * blo.w);
            *(float4*)&out0[t * 128 + ch] = make_float4(
                acc[0][tt][4] + biasScale * bhi.x, acc[0][tt][5] + biasScale * bhi.y,
                acc[0][tt][6] + biasScale * bhi.z, acc[0][tt][7] + biasScale * bhi.w);
        }
    } else if constexpr (EPI == 2) {
        float4 blo = *(const float4*)&bias[cl];
        float4 bhi = *(const float4*)&bias[ch];
#pragma unroll
        for (int tt = 0; tt < 4; tt++) {
            size_t t = m0 + tm * 4 + tt;
            float4 alo = *(const float4*)&add[t * 128 + cl];
            float4 ahi = *(const float4*)&add[t * 128 + ch];
            *(float4*)&out0[t * 128 + cl] = make_float4(
                silu_f(acc[0][tt][0] + blo.x + alo.x), silu_f(acc[0][tt][1] + blo.y + alo.y),
                silu_f(acc[0][tt][2] + blo.z + alo.z), silu_f(acc[0][tt][3] + blo.w + alo.w));
            *(float4*)&out0[t * 128 + ch] = make_float4(
                silu_f(acc[0][tt][4] + bhi.x + ahi.x), silu_f(acc[0][tt][5] + bhi.y + ahi.y),
                silu_f(acc[0][tt][6] + bhi.z + ahi.z), silu_f(acc[0][tt][7] + bhi.w + ahi.w));
        }
    } else {
        __shared__ float red1[64][17];
        __shared__ float red2[64][17];
        float4 blo = *(const float4*)&bias[cl];
        float4 bhi = *(const float4*)&bias[ch];
        float r[4][8];
#pragma unroll
        for (int tt = 0; tt < 4; tt++) {
            size_t t = m0 + tm * 4 + tt;
            float4 alo = *(const float4*)&add[t * 128 + cl];
            float4 ahi = *(const float4*)&add[t * 128 + ch];
            r[tt][0] = acc[0][tt][0] + blo.x + alo.x;
            r[tt][1] = acc[0][tt][1] + blo.y + alo.y;
            r[tt][2] = acc[0][tt][2] + blo.z + alo.z;
            r[tt][3] = acc[0][tt][3] + blo.w + alo.w;
            r[tt][4] = acc[0][tt][4] + bhi.x + ahi.x;
            r[tt][5] = acc[0][tt][5] + bhi.y + ahi.y;
            r[tt][6] = acc[0][tt][6] + bhi.z + ahi.z;
            r[tt][7] = acc[0][tt][7] + bhi.w + ahi.w;
            float s = 0.f, ss = 0.f;
#pragma unroll
            for (int e = 0; e < 8; e++) { s += r[tt][e]; ss += r[tt][e] * r[tt][e]; }
            red1[tm * 4 + tt][tn] = s;
            red2[tm * 4 + tt][tn] = ss;
        }
        __syncthreads();
        float4 glo = *(const float4*)&gamma[cl];
        float4 ghi = *(const float4*)&gamma[ch];
        float4 zlo = *(const float4*)&beta[cl];
        float4 zhi = *(const float4*)&beta[ch];
#pragma unroll
        for (int tt = 0; tt < 4; tt++) {
            int row = tm * 4 + tt;
            int t = m0 + row;
            float s = 0.f, ss = 0.f;
#pragma unroll
            for (int q = 0; q < 16; q++) { s += red1[row][q]; ss += red2[row][q]; }
            float mu = s * (1.f / 128.f);
            float var = ss * (1.f / 128.f) - mu * mu;
            float inv = rsqrtf(var + EPSc);
            int b = t / Nc;
            int node = tour[t];
            size_t base = ((size_t)b * Nc + node) * 128;
            *(float4*)&out0[base + cl] = make_float4(
                (r[tt][0] - mu) * inv * glo.x + zlo.x, (r[tt][1] - mu) * inv * glo.y + zlo.y,
                (r[tt][2] - mu) * inv * glo.z + zlo.z, (r[tt][3] - mu) * inv * glo.w + zlo.w);
            *(float4*)&out0[base + ch] = make_float4(
                (r[tt][4] - mu) * inv * ghi.x + zhi.x, (r[tt][5] - mu) * inv * ghi.y + zhi.y,
                (r[tt][6] - mu) * inv * ghi.z + zhi.z, (r[tt][7] - mu) * inv * ghi.w + zhi.w);
        }
    }
}

extern "C" void kernel_launch(void* const* d_in, const int* in_sizes, int n_in,
                              void* d_out, int out_size) {
    const float* h        = (const float*)d_in[0];
    const int*   tour_raw = (const int*)d_in[1];
    const float* W1m      = (const float*)d_in[2];
    const float* b1m      = (const float*)d_in[3];
    const float* W2m      = (const float*)d_in[4];
    const float* b2m      = (const float*)d_in[5];
    const float* W1u      = (const float*)d_in[6];
    const float* b1u      = (const float*)d_in[7];
    const float* W2u      = (const float*)d_in[8];
    const float* b2u      = (const float*)d_in[9];
    const float* gamma    = (const float*)d_in[10];
    const float* beta     = (const float*)d_in[11];
    float* out            = (float*)d_out;

    float *hpos, *A, *C, *P, *ys;
    int* tour;
    cudaGetSymbolAddress((void**)&hpos, g_hpos);
    cudaGetSymbolAddress((void**)&A,    g_A);
    cudaGetSymbolAddress((void**)&C,    g_C);
    cudaGetSymbolAddress((void**)&P,    g_P);
    cudaGetSymbolAddress((void**)&ys,   g_ys);
    cudaGetSymbolAddress((void**)&tour, g_tour);
    float* msg = ys;   // msg lives in g_ys
    float* t   = A;    // t overwrites A (A consumed by the roll-GEMM before)

    const int G = TOKc / 64;   // 2500 blocks

    // 0. normalize tour dtype
    k_detect<<<1, 1>>>(tour_raw);
    k_convert<<<(TOKc + 255) / 256, 256>>>(tour_raw, tour);

    // 1. [gather] A = hpos@W1m0, C = hpos@W1m1  (writes hpos too)
    k_fused<2, 1, 0><<<G, 256>>>(h, nullptr, W1m, W1m + 128 * 128,
                                 nullptr, nullptr, 0.f, nullptr,
                                 A, C, hpos, tour, nullptr, nullptr);
    // 2. P = hpos@W1u0
    k_fused<1, 0, 0><<<G, 256>>>(hpos, nullptr, W1u, nullptr,
                                 nullptr, nullptr, 0.f, nullptr,
                                 P, nullptr, nullptr, tour, nullptr, nullptr);
    // 3. [roll] msg = ys@W2m + 2*b2m   where ys = silu(A+C_prev+b1m)+silu(A+C_next+b1m)
    k_fused<1, 2, 1><<<G, 256>>>(A, C, W2m, nullptr,
                                 b2m, b1m, 2.f, nullptr,
                                 msg, nullptr, nullptr, tour, nullptr, nullptr);
    // 4. t = silu(P + msg@W1u1 + b1u)
    k_fused<1, 0, 2><<<G, 256>>>(msg, nullptr, W1u + 128 * 128, nullptr,
                                 b1u, nullptr, 0.f, P,
                                 t, nullptr, nullptr, tour, nullptr, nullptr);
    // 5. out[tour] = LN(hpos + t@W2u + b2u) * gamma + beta
    k_fused<1, 0, 3><<<G, 256>>>(t, nullptr, W2u, nullptr,
                                 b2u, nullptr, 0.f, hpos,
                                 out, nullptr, nullptr, tour, gamma, beta);
}

// round 4
// speedup vs baseline: 8.2120x; 1.0878x over previous
#include <cuda_runtime.h>
#include <cuda_bf16.h>
#include <cstdint>

#define Bc   16
#define Nc   10000
#define Dc   128
#define TOKc (Bc * Nc)          // 160000
#define EPSc 1e-5f
#define KC   32

// ---------------- scratch (no allocations allowed) ----------------
__device__ float g_hpos[(size_t)TOKc * Dc];
__device__ float g_A   [(size_t)TOKc * Dc];   // A, later t
__device__ float g_C   [(size_t)TOKc * Dc];   // C
__device__ float g_P   [(size_t)TOKc * Dc];   // P
__device__ float g_ys  [(size_t)TOKc * Dc];   // msg
__device__ int   g_tour[TOKc];
__device__ int   g_is64;

__device__ __forceinline__ float silu_f(float x) { return x / (1.f + __expf(-x)); }

// ---- packed f32x2 helpers (Blackwell FFMA2) ----
__device__ __forceinline__ unsigned long long pack2_dup(float x) {
    unsigned long long r;
    asm("mov.b64 %0, {%1, %1};" : "=l"(r) : "f"(x));
    return r;
}
__device__ __forceinline__ void fma2(unsigned long long& d, unsigned long long a, unsigned long long b) {
    asm("fma.rn.f32x2 %0, %1, %2, %0;" : "+l"(d) : "l"(a), "l"(b));
}
__device__ __forceinline__ void unpack2(unsigned long long v, float& lo, float& hi) {
    asm("mov.b64 {%0, %1}, %2;" : "=f"(lo), "=f"(hi) : "l"(v));
}

// ---- tour dtype detection: int64 values < 2^31 have zero odd 32-bit words ----
__global__ void k_detect(const int* __restrict__ tour_raw) {
    int allzero = 1;
    for (int i = 1; i < 129; i += 2) allzero &= (tour_raw[i] == 0);
    g_is64 = allzero;
}
__global__ void k_convert(const int* __restrict__ tour_raw, int* __restrict__ tour) {
    int t = blockIdx.x * blockDim.x + threadIdx.x;
    if (t >= TOKc) return;
    tour[t] = g_is64 ? tour_raw[2 * t] : tour_raw[t];
}

// ================= fused GEMM (FFMA2 micro-kernel) =================
// Tile: 64 tokens x 128 outputs. 256 threads: tn = tid&15 (col groups), tm = tid>>4.
// Thread computes 4 tokens x 8 cols (cols tn*4..+3 and 64+tn*4..+3) per weight set.
// PRO: 0 = direct X rows, 1 = gather via tour (+ write hpos), 2 = roll (ys from A,C,b1m)
// EPI: 0 = plain store (NSETS outputs), 1 = acc + biasScale*bias,
//      2 = silu(acc + bias + add), 3 = LayerNorm(acc + bias + add) * gamma + beta, scatter via tour
template<int NSETS, int PRO, int EPI>
__global__ void __launch_bounds__(256, 2)
k_fused(const float* __restrict__ X, const float* __restrict__ X2,
        const float* __restrict__ W0p, const float* __restrict__ W1p,
        const float* __restrict__ bias, const float* __restrict__ rbias, float biasScale,
        const float* __restrict__ add,
        float* __restrict__ out0, float* __restrict__ out1,
        float* __restrict__ hpos,
        const int* __restrict__ tour,
        const float* __restrict__ gamma, const float* __restrict__ beta) {
    __shared__ float Xs[KC][72];               // transposed X tile, padded
    __shared__ float Ws[NSETS][KC][128];

    const int tid = threadIdx.x;
    const int tn = tid & 15;
    const int tm = tid >> 4;
    const int m0 = blockIdx.x * 64;

    // acc2[s][tt][p]: p0=(cl,cl+1) p1=(cl+2,cl+3) p2=(ch,ch+1) p3=(ch+2,ch+3)
    unsigned long long acc2[NSETS][4][4];
#pragma unroll
    for (int s = 0; s < NSETS; s++)
#pragma unroll
        for (int tt = 0; tt < 4; tt++)
#pragma unroll
            for (int p = 0; p < 4; p++) acc2[s][tt][p] = 0ULL;

    for (int k0 = 0; k0 < 128; k0 += KC) {
        // ---- load X tile (64 rows x KC cols), store transposed ----
#pragma unroll
        for (int ff = 0; ff < 2; ff++) {
            int f = tid + ff * 256;            // 0..511
            int r = f >> 3, c4 = f & 7;
            int t = m0 + r;
            int col = k0 + c4 * 4;
            float4 v;
            if (PRO == 0) {
                v = *(const float4*)&X[(size_t)t * 128 + col];
            } else if (PRO == 1) {
                int b = t / Nc;
                int node = tour[t];
                v = *(const float4*)&X[((size_t)b * Nc + node) * 128 + col];
                *(float4*)&hpos[(size_t)t * 128 + col] = v;
            } else {
                int b = t / Nc, i = t - b * Nc;
                int tp = (i == 0)      ? t + Nc - 1 : t - 1;
                int tx = (i == Nc - 1) ? t - Nc + 1 : t + 1;
                float4 a  = *(const float4*)&X [(size_t)t  * 128 + col];
                float4 cp = *(const float4*)&X2[(size_t)tp * 128 + col];
                float4 cn = *(const float4*)&X2[(size_t)tx * 128 + col];
                float4 bb = *(const float4*)&rbias[col];
                v.x = silu_f(a.x + cp.x + bb.x) + silu_f(a.x + cn.x + bb.x);
                v.y = silu_f(a.y + cp.y + bb.y) + silu_f(a.y + cn.y + bb.y);
                v.z = silu_f(a.z + cp.z + bb.z) + silu_f(a.z + cn.z + bb.z);
                v.w = silu_f(a.w + cp.w + bb.w) + silu_f(a.w + cn.w + bb.w);
            }
            Xs[c4 * 4 + 0][r] = v.x;
            Xs[c4 * 4 + 1][r] = v.y;
            Xs[c4 * 4 + 2][r] = v.z;
            Xs[c4 * 4 + 3][r] = v.w;
        }
        // ---- load W tiles ----
#pragma unroll
        for (int ff = 0; ff < NSETS * 4; ff++) {
            int f = tid + ff * 256;            // < NSETS*1024
            int s = f >> 10;
            int r = (f >> 5) & 31;
            int c4 = f & 31;
            const float* Wp = (s == 0) ? W0p : W1p;
            *(float4*)&Ws[s][r][c4 * 4] = *(const float4*)&Wp[(size_t)(k0 + r) * 128 + c4 * 4];
        }
        __syncthreads();
        // ---- register-blocked outer product, packed f32x2 ----
#pragma unroll
        for (int kk = 0; kk < KC; kk++) {
            float4 xm4 = *(const float4*)&Xs[kk][tm * 4];
            unsigned long long xd[4];
            xd[0] = pack2_dup(xm4.x);
            xd[1] = pack2_dup(xm4.y);
            xd[2] = pack2_dup(xm4.z);
            xd[3] = pack2_dup(xm4.w);
#pragma unroll
            for (int s = 0; s < NSETS; s++) {
                ulonglong2 wa = *(const ulonglong2*)&Ws[s][kk][tn * 4];        // (w0,w1),(w2,w3)
                ulonglong2 wb = *(const ulonglong2*)&Ws[s][kk][64 + tn * 4];
#pragma unroll
                for (int tt = 0; tt < 4; tt++) {
                    fma2(acc2[s][tt][0], xd[tt], wa.x);
                    fma2(acc2[s][tt][1], xd[tt], wa.y);
                    fma2(acc2[s][tt][2], xd[tt], wb.x);
                    fma2(acc2[s][tt][3], xd[tt], wb.y);
                }
            }
        }
        __syncthreads();
    }

    // unpack accumulators
    float acc[NSETS][4][8];
#pragma unroll
    for (int s = 0; s < NSETS; s++)
#pragma unroll
        for (int tt = 0; tt < 4; tt++) {
            unpack2(acc2[s][tt][0], acc[s][tt][0], acc[s][tt][1]);
            unpack2(acc2[s][tt][1], acc[s][tt][2], acc[s][tt][3]);
            unpack2(acc2[s][tt][2], acc[s][tt][4], acc[s][tt][5]);
            unpack2(acc2[s][tt][3], acc[s][tt][6], acc[s][tt][7]);
        }

    const int cl = tn * 4, ch = 64 + tn * 4;

    if constexpr (EPI == 0) {
#pragma unroll
        for (int s = 0; s < NSETS; s++) {
            float* o = (s == 0) ? out0 : out1;
#pragma unroll
            for (int tt = 0; tt < 4; tt++) {
                size_t t = m0 + tm * 4 + tt;
                *(float4*)&o[t * 128 + cl] = make_float4(acc[s][tt][0], acc[s][tt][1], acc[s][tt][2], acc[s][tt][3]);
                *(float4*)&o[t * 128 + ch] = make_float4(acc[s][tt][4], acc[s][tt][5], acc[s][tt][6], acc[s][tt][7]);
            }
        }
    } else if constexpr (EPI == 1) {
        float4 blo = *(const float4*)&bias[cl];
        float4 bhi = *(const float4*)&bias[ch];
#pragma unroll
        for (int tt = 0; tt < 4; tt++) {
            size_t t = m0 + tm * 4 + tt;
            *(float4*)&out0[t * 128 + cl] = make_float4(
                acc[0][tt][0] + biasScale * blo.x, acc[0][tt][1] + biasScale * blo.y,
                acc[0][tt][2] + biasScale * blo.z, acc[0][tt][3] + biasScale * blo.w);
            *(float4*)&out0[t * 128 + ch] = make_float4(
                acc[0][tt][4] + biasScale * bhi.x, acc[0][tt][5] + biasScale * bhi.y,
                acc[0][tt][6] + biasScale * bhi.z, acc[0][tt][7] + biasScale * bhi.w);
        }
    } else if constexpr (EPI == 2) {
        float4 blo = *(const float4*)&bias[cl];
        float4 bhi = *(const float4*)&bias[ch];
#pragma unroll
        for (int tt = 0; tt < 4; tt++) {
            size_t t = m0 + tm * 4 + tt;
            float4 alo = *(const float4*)&add[t * 128 + cl];
            float4 ahi = *(const float4*)&add[t * 128 + ch];
            *(float4*)&out0[t * 128 + cl] = make_float4(
                silu_f(acc[0][tt][0] + blo.x + alo.x), silu_f(acc[0][tt][1] + blo.y + alo.y),
                silu_f(acc[0][tt][2] + blo.z + alo.z), silu_f(acc[0][tt][3] + blo.w + alo.w));
            *(float4*)&out0[t * 128 + ch] = make_float4(
                silu_f(acc[0][tt][4] + bhi.x + ahi.x), silu_f(acc[0][tt][5] + bhi.y + ahi.y),
                silu_f(acc[0][tt][6] + bhi.z + ahi.z), silu_f(acc[0][tt][7] + bhi.w + ahi.w));
        }
    } else {
        __shared__ float red1[64][17];
        __shared__ float red2[64][17];
        float4 blo = *(const float4*)&bias[cl];
        float4 bhi = *(const float4*)&bias[ch];
        float r[4][8];
#pragma unroll
        for (int tt = 0; tt < 4; tt++) {
            size_t t = m0 + tm * 4 + tt;
            float4 alo = *(const float4*)&add[t * 128 + cl];
            float4 ahi = *(const float4*)&add[t * 128 + ch];
            r[tt][0] = acc[0][tt][0] + blo.x + alo.x;
            r[tt][1] = acc[0][tt][1] + blo.y + alo.y;
            r[tt][2] = acc[0][tt][2] + blo.z + alo.z;
            r[tt][3] = acc[0][tt][3] + blo.w + alo.w;
            r[tt][4] = acc[0][tt][4] + bhi.x + ahi.x;
            r[tt][5] = acc[0][tt][5] + bhi.y + ahi.y;
            r[tt][6] = acc[0][tt][6] + bhi.z + ahi.z;
            r[tt][7] = acc[0][tt][7] + bhi.w + ahi.w;
            float s = 0.f, ss = 0.f;
#pragma unroll
            for (int e = 0; e < 8; e++) { s += r[tt][e]; ss += r[tt][e] * r[tt][e]; }
            red1[tm * 4 + tt][tn] = s;
            red2[tm * 4 + tt][tn] = ss;
        }
        __syncthreads();
        float4 glo = *(const float4*)&gamma[cl];
        float4 ghi = *(const float4*)&gamma[ch];
        float4 zlo = *(const float4*)&beta[cl];
        float4 zhi = *(const float4*)&beta[ch];
#pragma unroll
        for (int tt = 0; tt < 4; tt++) {
            int row = tm * 4 + tt;
            int t = m0 + row;
            float s = 0.f, ss = 0.f;
#pragma unroll
            for (int q = 0; q < 16; q++) { s += red1[row][q]; ss += red2[row][q]; }
            float mu = s * (1.f / 128.f);
            float var = ss * (1.f / 128.f) - mu * mu;
            float inv = rsqrtf(var + EPSc);
            int b = t / Nc;
            int node = tour[t];
            size_t base = ((size_t)b * Nc + node) * 128;
            *(float4*)&out0[base + cl] = make_float4(
                (r[tt][0] - mu) * inv * glo.x + zlo.x, (r[tt][1] - mu) * inv * glo.y + zlo.y,
                (r[tt][2] - mu) * inv * glo.z + zlo.z, (r[tt][3] - mu) * inv * glo.w + zlo.w);
            *(float4*)&out0[base + ch] = make_float4(
                (r[tt][4] - mu) * inv * ghi.x + zhi.x, (r[tt][5] - mu) * inv * ghi.y + zhi.y,
                (r[tt][6] - mu) * inv * ghi.z + zhi.z, (r[tt][7] - mu) * inv * ghi.w + zhi.w);
        }
    }
}

extern "C" void kernel_launch(void* const* d_in, const int* in_sizes, int n_in,
                              void* d_out, int out_size) {
    const float* h        = (const float*)d_in[0];
    const int*   tour_raw = (const int*)d_in[1];
    const float* W1m      = (const float*)d_in[2];
    const float* b1m      = (const float*)d_in[3];
    const float* W2m      = (const float*)d_in[4];
    const float* b2m      = (const float*)d_in[5];
    const float* W1u      = (const float*)d_in[6];
    const float* b1u      = (const float*)d_in[7];
    const float* W2u      = (const float*)d_in[8];
    const float* b2u      = (const float*)d_in[9];
    const float* gamma    = (const float*)d_in[10];
    const float* beta     = (const float*)d_in[11];
    float* out            = (float*)d_out;

    float *hpos, *A, *C, *P, *ys;
    int* tour;
    cudaGetSymbolAddress((void**)&hpos, g_hpos);
    cudaGetSymbolAddress((void**)&A,    g_A);
    cudaGetSymbolAddress((void**)&C,    g_C);
    cudaGetSymbolAddress((void**)&P,    g_P);
    cudaGetSymbolAddress((void**)&ys,   g_ys);
    cudaGetSymbolAddress((void**)&tour, g_tour);
    float* msg = ys;   // msg lives in g_ys
    float* t   = A;    // t overwrites A (A consumed by the roll-GEMM before)

    const int G = TOKc / 64;   // 2500 blocks

    // 0. normalize tour dtype
    k_detect<<<1, 1>>>(tour_raw);
    k_convert<<<(TOKc + 255) / 256, 256>>>(tour_raw, tour);

    // 1. [gather] A = hpos@W1m0, C = hpos@W1m1  (writes hpos too)
    k_fused<2, 1, 0><<<G, 256>>>(h, nullptr, W1m, W1m + 128 * 128,
                                 nullptr, nullptr, 0.f, nullptr,
                                 A, C, hpos, tour, nullptr, nullptr);
    // 2. P = hpos@W1u0
    k_fused<1, 0, 0><<<G, 256>>>(hpos, nullptr, W1u, nullptr,
                                 nullptr, nullptr, 0.f, nullptr,
                                 P, nullptr, nullptr, tour, nullptr, nullptr);
    // 3. [roll] msg = ys@W2m + 2*b2m   where ys = silu(A+C_prev+b1m)+silu(A+C_next+b1m)
    k_fused<1, 2, 1><<<G, 256>>>(A, C, W2m, nullptr,
                                 b2m, b1m, 2.f, nullptr,
                                 msg, nullptr, nullptr, tour, nullptr, nullptr);
    // 4. t = silu(P + msg@W1u1 + b1u)
    k_fused<1, 0, 2><<<G, 256>>>(msg, nullptr, W1u + 128 * 128, nullptr,
                                 b1u, nullptr, 0.f, P,
                                 t, nullptr, nullptr, tour, nullptr, nullptr);
    // 5. out[tour] = LN(hpos + t@W2u + b2u) * gamma + beta
    k_fused<1, 0, 3><<<G, 256>>>(t, nullptr, W2u, nullptr,
                                 b2u, nullptr, 0.f, hpos,
                                 out, nullptr, nullptr, tour, gamma, beta);
}

// round 5
// speedup vs baseline: 8.9113x; 1.0852x over previous
#include <cuda_runtime.h>
#include <cuda_bf16.h>
#include <cstdint>

#define Bc   16
#define Nc   10000
#define Dc   128
#define TOKc (Bc * Nc)          // 160000
#define EPSc 1e-5f
#define KC   32
#define XPAD 132                // 128 tokens + pad (2-way instead of 8-way STS conflict)

// ---------------- scratch (no allocations allowed) ----------------
__device__ float g_hpos[(size_t)TOKc * Dc];
__device__ float g_A   [(size_t)TOKc * Dc];   // A, later t
__device__ float g_C   [(size_t)TOKc * Dc];   // C
__device__ float g_P   [(size_t)TOKc * Dc];   // P
__device__ float g_ys  [(size_t)TOKc * Dc];   // msg
__device__ int   g_tour[TOKc];
__device__ int   g_is64;

__device__ __forceinline__ float silu_f(float x) { return x / (1.f + __expf(-x)); }

// ---- packed f32x2 helpers (Blackwell FFMA2) ----
__device__ __forceinline__ unsigned long long pack2_dup(float x) {
    unsigned long long r;
    asm("mov.b64 %0, {%1, %1};" : "=l"(r) : "f"(x));
    return r;
}
__device__ __forceinline__ void fma2(unsigned long long& d, unsigned long long a, unsigned long long b) {
    asm("fma.rn.f32x2 %0, %1, %2, %0;" : "+l"(d) : "l"(a), "l"(b));
}
__device__ __forceinline__ void unpack2(unsigned long long v, float& lo, float& hi) {
    asm("mov.b64 {%0, %1}, %2;" : "=f"(lo), "=f"(hi) : "l"(v));
}

// ---- tour dtype detection: int64 values < 2^31 have zero odd 32-bit words ----
__global__ void k_detect(const int* __restrict__ tour_raw) {
    int allzero = 1;
    for (int i = 1; i < 129; i += 2) allzero &= (tour_raw[i] == 0);
    g_is64 = allzero;
}
__global__ void k_convert(const int* __restrict__ tour_raw, int* __restrict__ tour) {
    int t = blockIdx.x * blockDim.x + threadIdx.x;
    if (t >= TOKc) return;
    tour[t] = g_is64 ? tour_raw[2 * t] : tour_raw[t];
}

// ================= fused GEMM (FFMA2, 128-token tiles, 8 tok x 8 col / thread) =================
// 256 threads: tn = tid&15 (col group: cols tn*4..+3 and 64+tn*4..+3), tm = tid>>4 (tokens tm*8..+7).
// PRO: 0 = direct X rows, 1 = gather via tour (+ write hpos), 2 = roll (ys from A,C,b1m)
// EPI: 0 = plain store (NSETS outputs), 1 = acc + biasScale*bias,
//      2 = silu(acc + bias + add), 3 = LayerNorm(acc + bias + add) * gamma + beta, scatter via tour
template<int NSETS, int PRO, int EPI, int MAXB>
__global__ void __launch_bounds__(256, MAXB)
k_fused(const float* __restrict__ X, const float* __restrict__ X2,
        const float* __restrict__ W0p, const float* __restrict__ W1p,
        const float* __restrict__ bias, const float* __restrict__ rbias, float biasScale,
        const float* __restrict__ add,
        float* __restrict__ out0, float* __restrict__ out1,
        float* __restrict__ hpos,
        const int* __restrict__ tour,
        const float* __restrict__ gamma, const float* __restrict__ beta) {
    __shared__ float Xs[KC][XPAD];             // transposed X tile (128 tokens)
    __shared__ float Ws[NSETS][KC][128];

    const int tid = threadIdx.x;
    const int tn = tid & 15;
    const int tm = tid >> 4;
    const int m0 = blockIdx.x * 128;

    // acc2[s][tt][p]: p0=(cl,cl+1) p1=(cl+2,cl+3) p2=(ch,ch+1) p3=(ch+2,ch+3)
    unsigned long long acc2[NSETS][8][4];
#pragma unroll
    for (int s = 0; s < NSETS; s++)
#pragma unroll
        for (int tt = 0; tt < 8; tt++)
#pragma unroll
            for (int p = 0; p < 4; p++) acc2[s][tt][p] = 0ULL;

    for (int k0 = 0; k0 < 128; k0 += KC) {
        // ---- load X tile (128 rows x KC cols), store transposed ----
#pragma unroll
        for (int ff = 0; ff < 4; ff++) {
            int f = tid + ff * 256;            // 0..1023
            int r = f >> 3, c4 = f & 7;
            int t = m0 + r;
            int col = k0 + c4 * 4;
            float4 v;
            if (PRO == 0) {
                v = *(const float4*)&X[(size_t)t * 128 + col];
            } else if (PRO == 1) {
                int b = t / Nc;
                int node = tour[t];
                v = *(const float4*)&X[((size_t)b * Nc + node) * 128 + col];
                *(float4*)&hpos[(size_t)t * 128 + col] = v;
            } else {
                int b = t / Nc, i = t - b * Nc;
                int tp = (i == 0)      ? t + Nc - 1 : t - 1;
                int tx = (i == Nc - 1) ? t - Nc + 1 : t + 1;
                float4 a  = *(const float4*)&X [(size_t)t  * 128 + col];
                float4 cp = *(const float4*)&X2[(size_t)tp * 128 + col];
                float4 cn = *(const float4*)&X2[(size_t)tx * 128 + col];
                float4 bb = *(const float4*)&rbias[col];
                v.x = silu_f(a.x + cp.x + bb.x) + silu_f(a.x + cn.x + bb.x);
                v.y = silu_f(a.y + cp.y + bb.y) + silu_f(a.y + cn.y + bb.y);
                v.z = silu_f(a.z + cp.z + bb.z) + silu_f(a.z + cn.z + bb.z);
                v.w = silu_f(a.w + cp.w + bb.w) + silu_f(a.w + cn.w + bb.w);
            }
            Xs[c4 * 4 + 0][r] = v.x;
            Xs[c4 * 4 + 1][r] = v.y;
            Xs[c4 * 4 + 2][r] = v.z;
            Xs[c4 * 4 + 3][r] = v.w;
        }
        // ---- load W tiles ----
#pragma unroll
        for (int ff = 0; ff < NSETS * 4; ff++) {
            int f = tid + ff * 256;            // < NSETS*1024
            int s = f >> 10;
            int r = (f >> 5) & 31;
            int c4 = f & 31;
            const float* Wp = (s == 0) ? W0p : W1p;
            *(float4*)&Ws[s][r][c4 * 4] = *(const float4*)&Wp[(size_t)(k0 + r) * 128 + c4 * 4];
        }
        __syncthreads();
        // ---- register-blocked outer product, packed f32x2 ----
#pragma unroll
        for (int kk = 0; kk < KC; kk++) {
            float4 xa = *(const float4*)&Xs[kk][tm * 8];
            float4 xb = *(const float4*)&Xs[kk][tm * 8 + 4];
            unsigned long long xd[8];
            xd[0] = pack2_dup(xa.x); xd[1] = pack2_dup(xa.y);
            xd[2] = pack2_dup(xa.z); xd[3] = pack2_dup(xa.w);
            xd[4] = pack2_dup(xb.x); xd[5] = pack2_dup(xb.y);
            xd[6] = pack2_dup(xb.z); xd[7] = pack2_dup(xb.w);
#pragma unroll
            for (int s = 0; s < NSETS; s++) {
                ulonglong2 wa = *(const ulonglong2*)&Ws[s][kk][tn * 4];
                ulonglong2 wb = *(const ulonglong2*)&Ws[s][kk][64 + tn * 4];
#pragma unroll
                for (int tt = 0; tt < 8; tt++) {
                    fma2(acc2[s][tt][0], xd[tt], wa.x);
                    fma2(acc2[s][tt][1], xd[tt], wa.y);
                    fma2(acc2[s][tt][2], xd[tt], wb.x);
                    fma2(acc2[s][tt][3], xd[tt], wb.y);
                }
            }
        }
        __syncthreads();
    }

    const int cl = tn * 4, ch = 64 + tn * 4;

    if constexpr (EPI == 0) {
#pragma unroll
        for (int s = 0; s < NSETS; s++) {
            float* o = (s == 0) ? out0 : out1;
#pragma unroll
            for (int tt = 0; tt < 8; tt++) {
                size_t t = m0 + tm * 8 + tt;
                float a0, a1, a2, a3, a4, a5, a6, a7;
                unpack2(acc2[s][tt][0], a0, a1); unpack2(acc2[s][tt][1], a2, a3);
                unpack2(acc2[s][tt][2], a4, a5); unpack2(acc2[s][tt][3], a6, a7);
                *(float4*)&o[t * 128 + cl] = make_float4(a0, a1, a2, a3);
                *(float4*)&o[t * 128 + ch] = make_float4(a4, a5, a6, a7);
            }
        }
    } else if constexpr (EPI == 1) {
        float4 blo = *(const float4*)&bias[cl];
        float4 bhi = *(const float4*)&bias[ch];
#pragma unroll
        for (int tt = 0; tt < 8; tt++) {
            size_t t = m0 + tm * 8 + tt;
            float a0, a1, a2, a3, a4, a5, a6, a7;
            unpack2(acc2[0][tt][0], a0, a1); unpack2(acc2[0][tt][1], a2, a3);
            unpack2(acc2[0][tt][2], a4, a5); unpack2(acc2[0][tt][3], a6, a7);
            *(float4*)&out0[t * 128 + cl] = make_float4(
                a0 + biasScale * blo.x, a1 + biasScale * blo.y,
                a2 + biasScale * blo.z, a3 + biasScale * blo.w);
            *(float4*)&out0[t * 128 + ch] = make_float4(
                a4 + biasScale * bhi.x, a5 + biasScale * bhi.y,
                a6 + biasScale * bhi.z, a7 + biasScale * bhi.w);
        }
    } else if constexpr (EPI == 2) {
        float4 blo = *(const float4*)&bias[cl];
        float4 bhi = *(const float4*)&bias[ch];
#pragma unroll
        for (int tt = 0; tt < 8; tt++) {
            size_t t = m0 + tm * 8 + tt;
            float4 alo = *(const float4*)&add[t * 128 + cl];
            float4 ahi = *(const float4*)&add[t * 128 + ch];
            float a0, a1, a2, a3, a4, a5, a6, a7;
            unpack2(acc2[0][tt][0], a0, a1); unpack2(acc2[0][tt][1], a2, a3);
            unpack2(acc2[0][tt][2], a4, a5); unpack2(acc2[0][tt][3], a6, a7);
            *(float4*)&out0[t * 128 + cl] = make_float4(
                silu_f(a0 + blo.x + alo.x), silu_f(a1 + blo.y + alo.y),
                silu_f(a2 + blo.z + alo.z), silu_f(a3 + blo.w + alo.w));
            *(float4*)&out0[t * 128 + ch] = make_float4(
                silu_f(a4 + bhi.x + ahi.x), silu_f(a5 + bhi.y + ahi.y),
                silu_f(a6 + bhi.z + ahi.z), silu_f(a7 + bhi.w + ahi.w));
        }
    } else {
        __shared__ float red1[128][17];
        __shared__ float red2[128][17];
        float4 blo = *(const float4*)&bias[cl];
        float4 bhi = *(const float4*)&bias[ch];
        float r[8][8];
#pragma unroll
        for (int tt = 0; tt < 8; tt++) {
            size_t t = m0 + tm * 8 + tt;
            float4 alo = *(const float4*)&add[t * 128 + cl];
            float4 ahi = *(const float4*)&add[t * 128 + ch];
            unpack2(acc2[0][tt][0], r[tt][0], r[tt][1]);
            unpack2(acc2[0][tt][1], r[tt][2], r[tt][3]);
            unpack2(acc2[0][tt][2], r[tt][4], r[tt][5]);
            unpack2(acc2[0][tt][3], r[tt][6], r[tt][7]);
            r[tt][0] += blo.x + alo.x;  r[tt][1] += blo.y + alo.y;
            r[tt][2] += blo.z + alo.z;  r[tt][3] += blo.w + alo.w;
            r[tt][4] += bhi.x + ahi.x;  r[tt][5] += bhi.y + ahi.y;
            r[tt][6] += bhi.z + ahi.z;  r[tt][7] += bhi.w + ahi.w;
            float s = 0.f, ss = 0.f;
#pragma unroll
            for (int e = 0; e < 8; e++) { s += r[tt][e]; ss += r[tt][e] * r[tt][e]; }
            red1[tm * 8 + tt][tn] = s;
            red2[tm * 8 + tt][tn] = ss;
        }
        __syncthreads();
        float4 glo = *(const float4*)&gamma[cl];
        float4 ghi = *(const float4*)&gamma[ch];
        float4 zlo = *(const float4*)&beta[cl];
        float4 zhi = *(const float4*)&beta[ch];
#pragma unroll
        for (int tt = 0; tt < 8; tt++) {
            int row = tm * 8 + tt;
            int t = m0 + row;
            float s = 0.f, ss = 0.f;
#pragma unroll
            for (int q = 0; q < 16; q++) { s += red1[row][q]; ss += red2[row][q]; }
            float mu = s * (1.f / 128.f);
            float var = ss * (1.f / 128.f) - mu * mu;
            float inv = rsqrtf(var + EPSc);
            int b = t / Nc;
            int node = tour[t];
            size_t base = ((size_t)b * Nc + node) * 128;
            *(float4*)&out0[base + cl] = make_float4(
                (r[tt][0] - mu) * inv * glo.x + zlo.x, (r[tt][1] - mu) * inv * glo.y + zlo.y,
                (r[tt][2] - mu) * inv * glo.z + zlo.z, (r[tt][3] - mu) * inv * glo.w + zlo.w);
            *(float4*)&out0[base + ch] = make_float4(
                (r[tt][4] - mu) * inv * ghi.x + zhi.x, (r[tt][5] - mu) * inv * ghi.y + zhi.y,
                (r[tt][6] - mu) * inv * ghi.z + zhi.z, (r[tt][7] - mu) * inv * ghi.w + zhi.w);
        }
    }
}

extern "C" void kernel_launch(void* const* d_in, const int* in_sizes, int n_in,
                              void* d_out, int out_size) {
    const float* h        = (const float*)d_in[0];
    const int*   tour_raw = (const int*)d_in[1];
    const float* W1m      = (const float*)d_in[2];
    const float* b1m      = (const float*)d_in[3];
    const float* W2m      = (const float*)d_in[4];
    const float* b2m      = (const float*)d_in[5];
    const float* W1u      = (const float*)d_in[6];
    const float* b1u      = (const float*)d_in[7];
    const float* W2u      = (const float*)d_in[8];
    const float* b2u      = (const float*)d_in[9];
    const float* gamma    = (const float*)d_in[10];
    const float* beta     = (const float*)d_in[11];
    float* out            = (float*)d_out;

    float *hpos, *A, *C, *P, *ys;
    int* tour;
    cudaGetSymbolAddress((void**)&hpos, g_hpos);
    cudaGetSymbolAddress((void**)&A,    g_A);
    cudaGetSymbolAddress((void**)&C,    g_C);
    cudaGetSymbolAddress((void**)&P,    g_P);
    cudaGetSymbolAddress((void**)&ys,   g_ys);
    cudaGetSymbolAddress((void**)&tour, g_tour);
    float* msg = ys;   // msg lives in g_ys
    float* t   = A;    // t overwrites A (A consumed by the roll-GEMM before)

    const int G = TOKc / 128;   // 1250 blocks

    // 0. normalize tour dtype
    k_detect<<<1, 1>>>(tour_raw);
    k_convert<<<(TOKc + 255) / 256, 256>>>(tour_raw, tour);

    // 1. [gather] A = hpos@W1m0, C = hpos@W1m1  (writes hpos too)
    k_fused<2, 1, 0, 1><<<G, 256>>>(h, nullptr, W1m, W1m + 128 * 128,
                                    nullptr, nullptr, 0.f, nullptr,
                                    A, C, hpos, tour, nullptr, nullptr);
    // 2. P = hpos@W1u0
    k_fused<1, 0, 0, 2><<<G, 256>>>(hpos, nullptr, W1u, nullptr,
                                    nullptr, nullptr, 0.f, nullptr,
                                    P, nullptr, nullptr, tour, nullptr, nullptr);
    // 3. [roll] msg = ys@W2m + 2*b2m   where ys = silu(A+C_prev+b1m)+silu(A+C_next+b1m)
    k_fused<1, 2, 1, 2><<<G, 256>>>(A, C, W2m, nullptr,
                                    b2m, b1m, 2.f, nullptr,
                                    msg, nullptr, nullptr, tour, nullptr, nullptr);
    // 4. t = silu(P + msg@W1u1 + b1u)
    k_fused<1, 0, 2, 2><<<G, 256>>>(msg, nullptr, W1u + 128 * 128, nullptr,
                                    b1u, nullptr, 0.f, P,
                                    t, nullptr, nullptr, tour, nullptr, nullptr);
    // 5. out[tour] = LN(hpos + t@W2u + b2u) * gamma + beta
    k_fused<1, 0, 3, 2><<<G, 256>>>(t, nullptr, W2u, nullptr,
                                    b2u, nullptr, 0.f, hpos,
                                    out, nullptr, nullptr, tour, gamma, beta);
}